// round 10
// baseline (speedup 1.0000x reference)
#include <cuda_runtime.h>
#include <cuda_bf16.h>
#include <cstdint>

#define NIN 7
#define H   32
#define TPB 128
#define ITERS 4          // 128 samples per CTA per iter

typedef unsigned long long u64;
typedef unsigned int u32;

// ---------------- constant weight image --------------------------------------
//  float4 idx: [0,56) w0t pairs ; [312,320) b0 ; floats: b1 @1280, w2 @1312, b2 @1344
__constant__ float4 CW4[337];
__device__ float DSTG[1348];
// B fragments for mma.m16n8k16 (per-lane, PTX fragment layout):
// tile t = hl*8 + kt*4 + nt ; BFG[t*32 + lane] = {b0b1, b2b3}
__device__ uint2 BFG[512];

typedef union { float4 f; ulonglong2 u; } F4U;
__device__ __forceinline__ ulonglong2 ldc4(int idx) { F4U t; t.f = CW4[idx]; return t.u; }
__device__ __forceinline__ float cwf(int fidx) { return ((const float*)CW4)[fidx]; }

// ---------------- scalar helpers ----------------
__device__ __forceinline__ u64 pk2(float a, float b) {
    u64 r; asm("mov.b64 %0, {%1, %2};" : "=l"(r) : "f"(a), "f"(b)); return r;
}
__device__ __forceinline__ float2 upk2(u64 v) {
    float2 f; asm("mov.b64 {%0, %1}, %2;" : "=f"(f.x), "=f"(f.y) : "l"(v)); return f;
}
__device__ __forceinline__ u64 ffma2(u64 a, u64 b, u64 c) {
    u64 r; asm("fma.rn.f32x2 %0, %1, %2, %3;" : "=l"(r) : "l"(a), "l"(b), "l"(c)); return r;
}
__device__ __forceinline__ float tanh_approx(float x) {
    float r; asm("tanh.approx.f32 %0, %1;" : "=f"(r) : "f"(x)); return r;
}
// lower 16 bits = bf16(a), upper = bf16(b)
__device__ __forceinline__ u32 bf16x2_of(float a, float b) {
    u32 r; asm("cvt.rn.bf16x2.f32 %0, %1, %2;" : "=r"(r) : "f"(b), "f"(a)); return r;
}
__device__ __forceinline__ u32 smem_u32(const void* p) {
    u32 a; asm("{ .reg .u64 t; cvta.to.shared.u64 t, %1; cvt.u32.u64 %0, t; }"
               : "=r"(a) : "l"(p));
    return a;
}
__device__ __forceinline__ void ldsm4(u32* r, u32 addr) {
    asm volatile("ldmatrix.sync.aligned.m8n8.x4.shared.b16 {%0,%1,%2,%3}, [%4];"
                 : "=r"(r[0]), "=r"(r[1]), "=r"(r[2]), "=r"(r[3]) : "r"(addr));
}
__device__ __forceinline__ void mma_bf16(float* d, const u32* a, uint2 b) {
    asm volatile(
        "mma.sync.aligned.m16n8k16.row.col.f32.bf16.bf16.f32 "
        "{%0,%1,%2,%3}, {%4,%5,%6,%7}, {%8,%9}, {%0,%1,%2,%3};"
        : "+f"(d[0]), "+f"(d[1]), "+f"(d[2]), "+f"(d[3])
        : "r"(a[0]), "r"(a[1]), "r"(a[2]), "r"(a[3]), "r"(b.x), "r"(b.y));
}

// ---------------- prep kernel ----------------
__global__ void prep_kernel(const float* __restrict__ w0, const float* __restrict__ b0,
                            const float* __restrict__ w1, const float* __restrict__ b1,
                            const float* __restrict__ w2, const float* __restrict__ b2)
{
    int g = blockIdx.x * blockDim.x + threadIdx.x;
    int stride = gridDim.x * blockDim.x;

    for (int k = g; k < 1348; k += stride) {
        if (k < 224) {                       // w0t[i*32+h] = w0[h][i]
            int i = k >> 5, h = k & 31;
            DSTG[k] = w0[h * NIN + i];
        } else if (k < 1248) {               // w1t (layout stability, unused)
            int kk = k - 224;
            int i = kk >> 5, h = kk & 31;
            DSTG[k] = w1[h * H + i];
        } else if (k < 1280) DSTG[k] = b0[k - 1248];
        else if (k < 1312)   DSTG[k] = b1[k - 1280];
        else if (k < 1344)   DSTG[k] = w2[k - 1312];
        else                 DSTG[k] = b2[0];
    }

    // B fragments: B[k][n] = w1[n][k]; PTX m16n8k16 layout:
    //   n = 8*nt + lane/4 ; k0 = 16*kt + 2*(lane%4)
    for (int idx = g; idx < 512; idx += stride) {
        int t = idx >> 5, l = idx & 31;
        int hl = t >> 3, kt = (t >> 2) & 1, nt = t & 3;
        int n = 8 * nt + (l >> 2);
        int k0 = 16 * kt + 2 * (l & 3);

        int ks[4] = { k0, k0 + 1, k0 + 8, k0 + 9 };
        u32 p[4];
        for (int j = 0; j < 4; ++j) {
            float w = w1[n * H + ks[j]];
            __nv_bfloat16 hi = __float2bfloat16(w);
            if (hl == 0) {
                union { __nv_bfloat16 h; unsigned short s; } c; c.h = hi; p[j] = c.s;
            } else {
                __nv_bfloat16 lo = __float2bfloat16(w - __bfloat162float(hi));
                union { __nv_bfloat16 h; unsigned short s; } c; c.h = lo; p[j] = c.s;
            }
        }
        BFG[idx] = make_uint2(p[0] | (p[1] << 16), p[2] | (p[3] << 16));
    }
}

// ---------------- main kernel ----------------
__global__ __launch_bounds__(TPB, 5)
void WarpTileMLP_kernel(const float* __restrict__ q, float* __restrict__ out)
{
    // per-warp staging: Z_hi 32x32 bf16 (64B rows) + Z_lo, XOR-swizzled chunks
    __shared__ __align__(16) char zstage[4][4096];

    const int tid  = threadIdx.x;
    const int wid  = tid >> 5;
    const int lane = tid & 31;

    const u32 zh = smem_u32(&zstage[wid][0]);
    const u32 zl = zh + 2048;

    // STS offsets: row = lane, chunk c stored at c ^ ((row>>1)&3)
    u32 sts_off[4];
#pragma unroll
    for (int c = 0; c < 4; ++c)
        sts_off[c] = (u32)lane * 64u + (u32)((c ^ ((lane >> 1) & 3)) * 16);

    // ldmatrix offsets for A tile (mt, kt)
    u32 lds_off[2][2];
    {
        int r16 = lane & 15, cb = lane >> 4;
#pragma unroll
        for (int mt = 0; mt < 2; ++mt)
#pragma unroll
            for (int kt = 0; kt < 2; ++kt)
                lds_off[mt][kt] = (u32)((16 * mt + r16) * 64 +
                                        (((2 * kt + cb) ^ ((r16 >> 1) & 3)) * 16));
    }

    // per-lane b1/w2 for epilogue: col(nt,j) = 8nt + 2*(lane&3) + j
    float b1c[8], w2c[8];
#pragma unroll
    for (int nt = 0; nt < 4; ++nt)
#pragma unroll
        for (int j = 0; j < 2; ++j) {
            int col = 8 * nt + 2 * (lane & 3) + j;
            b1c[nt * 2 + j] = cwf(1280 + col);
            w2c[nt * 2 + j] = cwf(1312 + col);
        }
    const float b2v = cwf(1344);

    const uint2* bgp = BFG + lane;

    // prefetch iter-0 inputs
    float x[NIN];
    {
        const float* qr = q + (((long)blockIdx.x * ITERS) * TPB + wid * 32 + lane) * NIN;
#pragma unroll
        for (int i = 0; i < NIN; ++i) x[i] = __ldg(qr + i);
    }

    for (int it = 0; it < ITERS; ++it) {
        const long sbase = (((long)blockIdx.x * ITERS + it) * TPB) + wid * 32;

        // ---- layer 0 (1 sample/thread), constant weights, f32x2 ----
        u64 acc[16];
#pragma unroll
        for (int pp = 0; pp < 8; ++pp) {
            ulonglong2 bb = ldc4(312 + pp);
            acc[2 * pp] = bb.x; acc[2 * pp + 1] = bb.y;
        }
#pragma unroll
        for (int i = 0; i < NIN; ++i) {
            u64 xd = pk2(x[i], x[i]);
#pragma unroll
            for (int c = 0; c < 8; ++c) {
                ulonglong2 w = ldc4(i * 8 + c);
                acc[2 * c]     = ffma2(w.x, xd, acc[2 * c]);
                acc[2 * c + 1] = ffma2(w.y, xd, acc[2 * c + 1]);
            }
        }

        // ---- prefetch next iter's inputs (hidden behind tanh/STS/MMA) ----
        if (it + 1 < ITERS) {
            const float* qn = q + (sbase + TPB + lane) * NIN;
#pragma unroll
            for (int i = 0; i < NIN; ++i) x[i] = __ldg(qn + i);
        }

        // ---- tanh -> bf16 hi/lo split ----
        u32 hib[16], lob[16];
#pragma unroll
        for (int p = 0; p < 16; ++p) {
            float2 z = upk2(acc[p]);
            float t0 = tanh_approx(z.x), t1 = tanh_approx(z.y);
            u32 hi = bf16x2_of(t0, t1);
            float h0 = __uint_as_float(hi << 16);
            float h1 = __uint_as_float(hi & 0xFFFF0000u);
            hib[p] = hi;
            lob[p] = bf16x2_of(t0 - h0, t1 - h1);
        }

        // ---- stage to warp-private smem (swizzled 16B chunks) ----
#pragma unroll
        for (int c = 0; c < 4; ++c) {
            asm volatile("st.shared.v4.b32 [%0], {%1,%2,%3,%4};" ::
                "r"(zh + sts_off[c]), "r"(hib[4*c]), "r"(hib[4*c+1]),
                "r"(hib[4*c+2]), "r"(hib[4*c+3]) : "memory");
            asm volatile("st.shared.v4.b32 [%0], {%1,%2,%3,%4};" ::
                "r"(zl + sts_off[c]), "r"(lob[4*c]), "r"(lob[4*c+1]),
                "r"(lob[4*c+2]), "r"(lob[4*c+3]) : "memory");
        }
        __syncwarp();

        // ---- load A fragments ----
        u32 AH[2][2][4], AL[2][2][4];
#pragma unroll
        for (int mt = 0; mt < 2; ++mt)
#pragma unroll
            for (int kt = 0; kt < 2; ++kt) {
                ldsm4(AH[mt][kt], zh + lds_off[mt][kt]);
                ldsm4(AL[mt][kt], zl + lds_off[mt][kt]);
            }
        __syncwarp();

        // ---- layer 1 MMA + fused layer 2 epilogue; B frags loaded per nt ----
        u64 rs2[4];
#pragma unroll
        for (int j = 0; j < 4; ++j) rs2[j] = pk2(0.0f, 0.0f);

#pragma unroll
        for (int nt = 0; nt < 4; ++nt) {
            uint2 bh0 = bgp[(0 + nt) * 32];    // W_hi, k-tile 0
            uint2 bh1 = bgp[(4 + nt) * 32];    // W_hi, k-tile 1
            uint2 bl0 = bgp[(8 + nt) * 32];    // W_lo, k-tile 0
            uint2 bl1 = bgp[(12 + nt) * 32];   // W_lo, k-tile 1
#pragma unroll
            for (int mt = 0; mt < 2; ++mt) {
                float d[4] = {0.0f, 0.0f, 0.0f, 0.0f};
                mma_bf16(d, AH[mt][0], bh0);       // Z_hi @ W_hi (k0)
                mma_bf16(d, AH[mt][1], bh1);       // Z_hi @ W_hi (k1)
                mma_bf16(d, AL[mt][0], bh0);       // Z_lo @ W_hi (k0)
                mma_bf16(d, AL[mt][1], bh1);       // Z_lo @ W_hi (k1)
                mma_bf16(d, AH[mt][0], bl0);       // Z_hi @ W_lo (k0)
                mma_bf16(d, AH[mt][1], bl1);       // Z_hi @ W_lo (k1)

                float t0 = tanh_approx(d[0] + b1c[2 * nt]);
                float t1 = tanh_approx(d[1] + b1c[2 * nt + 1]);
                rs2[2 * mt] = ffma2(pk2(w2c[2 * nt], w2c[2 * nt + 1]),
                                    pk2(t0, t1), rs2[2 * mt]);
                float t2 = tanh_approx(d[2] + b1c[2 * nt]);
                float t3 = tanh_approx(d[3] + b1c[2 * nt + 1]);
                rs2[2 * mt + 1] = ffma2(pk2(w2c[2 * nt], w2c[2 * nt + 1]),
                                        pk2(t2, t3), rs2[2 * mt + 1]);
            }
        }

        // ---- quad reduce + store ----
        float rs[4];
#pragma unroll
        for (int j = 0; j < 4; ++j) {
            float2 p = upk2(rs2[j]);
            float v = p.x + p.y;
            v += __shfl_xor_sync(0xffffffffu, v, 1);
            v += __shfl_xor_sync(0xffffffffu, v, 2);
            rs[j] = v;
        }
        const int row = (lane >> 2) + 8 * (lane & 3);
        out[sbase + row] = rs[lane & 3] + b2v;
    }
}

extern "C" void kernel_launch(void* const* d_in, const int* in_sizes, int n_in,
                              void* d_out, int out_size)
{
    const float* q  = (const float*)d_in[0];
    const float* w0 = (const float*)d_in[1];
    const float* b0 = (const float*)d_in[2];
    const float* w1 = (const float*)d_in[3];
    const float* b1 = (const float*)d_in[4];
    const float* w2 = (const float*)d_in[5];
    const float* b2 = (const float*)d_in[6];
    float* out = (float*)d_out;

    prep_kernel<<<17, TPB>>>(w0, b0, w1, b1, w2, b2);

    void* sym = nullptr; void* stg = nullptr;
    cudaGetSymbolAddress(&sym, CW4);
    cudaGetSymbolAddress(&stg, DSTG);
    cudaMemcpyAsync(sym, stg, 1348 * sizeof(float), cudaMemcpyDeviceToDevice);

    const int B = in_sizes[0] / NIN;                 // 2097152
    const int blocks = B / (TPB * ITERS);            // 4096
    WarpTileMLP_kernel<<<blocks, TPB>>>(q, out);
}

// round 11
// speedup vs baseline: 1.0625x; 1.0625x over previous
#include <cuda_runtime.h>
#include <cuda_bf16.h>
#include <cstdint>

#define NIN 7
#define H   32
#define TPB 128
#define ITERS 4          // 128 samples per CTA per iter

typedef unsigned long long u64;
typedef unsigned int u32;

// ---------------- constant weight image --------------------------------------
//  float4 idx: [0,56) w0t pairs ; [312,320) b0 ; floats: b1 @1280, w2 @1312, b2 @1344
__constant__ float4 CW4[337];
__device__ float DSTG[1348];
// B fragments for mma.m16n8k16 (per-lane, PTX fragment layout):
// tile t = hl*8 + kt*4 + nt ; BFG[t*32 + lane] = {b0b1, b2b3}
__device__ uint2 BFG[512];

typedef union { float4 f; ulonglong2 u; } F4U;
__device__ __forceinline__ ulonglong2 ldc4(int idx) { F4U t; t.f = CW4[idx]; return t.u; }
__device__ __forceinline__ float cwf(int fidx) { return ((const float*)CW4)[fidx]; }

// ---------------- scalar helpers ----------------
__device__ __forceinline__ u64 pk2(float a, float b) {
    u64 r; asm("mov.b64 %0, {%1, %2};" : "=l"(r) : "f"(a), "f"(b)); return r;
}
__device__ __forceinline__ float2 upk2(u64 v) {
    float2 f; asm("mov.b64 {%0, %1}, %2;" : "=f"(f.x), "=f"(f.y) : "l"(v)); return f;
}
__device__ __forceinline__ u64 ffma2(u64 a, u64 b, u64 c) {
    u64 r; asm("fma.rn.f32x2 %0, %1, %2, %3;" : "=l"(r) : "l"(a), "l"(b), "l"(c)); return r;
}
__device__ __forceinline__ float tanh_approx(float x) {
    float r; asm("tanh.approx.f32 %0, %1;" : "=f"(r) : "f"(x)); return r;
}
// lower 16 bits = bf16(a), upper = bf16(b)
__device__ __forceinline__ u32 bf16x2_of(float a, float b) {
    u32 r; asm("cvt.rn.bf16x2.f32 %0, %1, %2;" : "=r"(r) : "f"(b), "f"(a)); return r;
}
__device__ __forceinline__ u32 smem_u32(const void* p) {
    u32 a; asm("{ .reg .u64 t; cvta.to.shared.u64 t, %1; cvt.u32.u64 %0, t; }"
               : "=r"(a) : "l"(p));
    return a;
}
__device__ __forceinline__ void ldsm4(u32* r, u32 addr) {
    asm volatile("ldmatrix.sync.aligned.m8n8.x4.shared.b16 {%0,%1,%2,%3}, [%4];"
                 : "=r"(r[0]), "=r"(r[1]), "=r"(r[2]), "=r"(r[3]) : "r"(addr));
}
__device__ __forceinline__ void mma_bf16(float* d, const u32* a, uint2 b) {
    asm volatile(
        "mma.sync.aligned.m16n8k16.row.col.f32.bf16.bf16.f32 "
        "{%0,%1,%2,%3}, {%4,%5,%6,%7}, {%8,%9}, {%0,%1,%2,%3};"
        : "+f"(d[0]), "+f"(d[1]), "+f"(d[2]), "+f"(d[3])
        : "r"(a[0]), "r"(a[1]), "r"(a[2]), "r"(a[3]), "r"(b.x), "r"(b.y));
}

// ---------------- prep kernel ----------------
__global__ void prep_kernel(const float* __restrict__ w0, const float* __restrict__ b0,
                            const float* __restrict__ w1, const float* __restrict__ b1,
                            const float* __restrict__ w2, const float* __restrict__ b2)
{
    int g = blockIdx.x * blockDim.x + threadIdx.x;
    int stride = gridDim.x * blockDim.x;

    for (int k = g; k < 1348; k += stride) {
        if (k < 224) {                       // w0t[i*32+h] = w0[h][i]
            int i = k >> 5, h = k & 31;
            DSTG[k] = w0[h * NIN + i];
        } else if (k < 1248) {               // w1t (layout stability, unused)
            int kk = k - 224;
            int i = kk >> 5, h = kk & 31;
            DSTG[k] = w1[h * H + i];
        } else if (k < 1280) DSTG[k] = b0[k - 1248];
        else if (k < 1312)   DSTG[k] = b1[k - 1280];
        else if (k < 1344)   DSTG[k] = w2[k - 1312];
        else                 DSTG[k] = b2[0];
    }

    // B fragments: B[k][n] = w1[n][k]; PTX m16n8k16 layout:
    //   n = 8*nt + lane/4 ; k0 = 16*kt + 2*(lane%4)
    for (int idx = g; idx < 512; idx += stride) {
        int t = idx >> 5, l = idx & 31;
        int hl = t >> 3, kt = (t >> 2) & 1, nt = t & 3;
        int n = 8 * nt + (l >> 2);
        int k0 = 16 * kt + 2 * (l & 3);

        int ks[4] = { k0, k0 + 1, k0 + 8, k0 + 9 };
        u32 p[4];
        for (int j = 0; j < 4; ++j) {
            float w = w1[n * H + ks[j]];
            __nv_bfloat16 hi = __float2bfloat16(w);
            if (hl == 0) {
                union { __nv_bfloat16 h; unsigned short s; } c; c.h = hi; p[j] = c.s;
            } else {
                __nv_bfloat16 lo = __float2bfloat16(w - __bfloat162float(hi));
                union { __nv_bfloat16 h; unsigned short s; } c; c.h = lo; p[j] = c.s;
            }
        }
        BFG[idx] = make_uint2(p[0] | (p[1] << 16), p[2] | (p[3] << 16));
    }
}

// ---------------- main kernel ----------------
__global__ __launch_bounds__(TPB, 4)
void WarpTileMLP_kernel(const float* __restrict__ q, float* __restrict__ out)
{
    // per-warp staging: Z_hi 32x32 bf16 (64B rows) + Z_lo, XOR-swizzled chunks
    __shared__ __align__(16) char zstage[4][4096];

    const int tid  = threadIdx.x;
    const int wid  = tid >> 5;
    const int lane = tid & 31;

    const u32 zh = smem_u32(&zstage[wid][0]);
    const u32 zl = zh + 2048;

    // STS offsets: row = lane, chunk c stored at c ^ ((row>>1)&3)
    u32 sts_off[4];
#pragma unroll
    for (int c = 0; c < 4; ++c)
        sts_off[c] = (u32)lane * 64u + (u32)((c ^ ((lane >> 1) & 3)) * 16);

    // ldmatrix offsets for A tile (mt, kt)
    u32 lds_off[2][2];
    {
        int r16 = lane & 15, cb = lane >> 4;
#pragma unroll
        for (int mt = 0; mt < 2; ++mt)
#pragma unroll
            for (int kt = 0; kt < 2; ++kt)
                lds_off[mt][kt] = (u32)((16 * mt + r16) * 64 +
                                        (((2 * kt + cb) ^ ((r16 >> 1) & 3)) * 16));
    }

    // per-lane b1/w2 for epilogue: col(nt,j) = 8nt + 2*(lane&3) + j
    float b1c[8], w2c[8];
#pragma unroll
    for (int nt = 0; nt < 4; ++nt)
#pragma unroll
        for (int j = 0; j < 2; ++j) {
            int col = 8 * nt + 2 * (lane & 3) + j;
            b1c[nt * 2 + j] = cwf(1280 + col);
            w2c[nt * 2 + j] = cwf(1312 + col);
        }
    const float b2v = cwf(1344);

    // prefetch iter-0 inputs
    float x[NIN];
    {
        const float* qr = q + (((long)blockIdx.x * ITERS) * TPB + wid * 32 + lane) * NIN;
#pragma unroll
        for (int i = 0; i < NIN; ++i) x[i] = __ldg(qr + i);
    }

    for (int it = 0; it < ITERS; ++it) {
        const long sbase = (((long)blockIdx.x * ITERS + it) * TPB) + wid * 32;

        // ---- layer 0 (1 sample/thread), constant weights, f32x2 ----
        u64 acc[16];
#pragma unroll
        for (int pp = 0; pp < 8; ++pp) {
            ulonglong2 bb = ldc4(312 + pp);
            acc[2 * pp] = bb.x; acc[2 * pp + 1] = bb.y;
        }
#pragma unroll
        for (int i = 0; i < NIN; ++i) {
            u64 xd = pk2(x[i], x[i]);
#pragma unroll
            for (int c = 0; c < 8; ++c) {
                ulonglong2 w = ldc4(i * 8 + c);
                acc[2 * c]     = ffma2(w.x, xd, acc[2 * c]);
                acc[2 * c + 1] = ffma2(w.y, xd, acc[2 * c + 1]);
            }
        }

        // ---- prefetch next iter's inputs (x is dead; hides DRAM latency
        //      behind tanh/STS/ldsm/MMA of the current iteration) ----
        if (it + 1 < ITERS) {
            const float* qn = q + (sbase + TPB + lane) * NIN;
#pragma unroll
            for (int i = 0; i < NIN; ++i) x[i] = __ldg(qn + i);
        }

        // ---- tanh -> bf16 hi/lo split ----
        u32 hib[16], lob[16];
#pragma unroll
        for (int p = 0; p < 16; ++p) {
            float2 z = upk2(acc[p]);
            float t0 = tanh_approx(z.x), t1 = tanh_approx(z.y);
            u32 hi = bf16x2_of(t0, t1);
            float h0 = __uint_as_float(hi << 16);
            float h1 = __uint_as_float(hi & 0xFFFF0000u);
            hib[p] = hi;
            lob[p] = bf16x2_of(t0 - h0, t1 - h1);
        }

        // ---- stage to warp-private smem (swizzled 16B chunks) ----
#pragma unroll
        for (int c = 0; c < 4; ++c) {
            asm volatile("st.shared.v4.b32 [%0], {%1,%2,%3,%4};" ::
                "r"(zh + sts_off[c]), "r"(hib[4*c]), "r"(hib[4*c+1]),
                "r"(hib[4*c+2]), "r"(hib[4*c+3]) : "memory");
            asm volatile("st.shared.v4.b32 [%0], {%1,%2,%3,%4};" ::
                "r"(zl + sts_off[c]), "r"(lob[4*c]), "r"(lob[4*c+1]),
                "r"(lob[4*c+2]), "r"(lob[4*c+3]) : "memory");
        }
        __syncwarp();

        // ---- load A fragments ----
        u32 AH[2][2][4], AL[2][2][4];
#pragma unroll
        for (int mt = 0; mt < 2; ++mt)
#pragma unroll
            for (int kt = 0; kt < 2; ++kt) {
                ldsm4(AH[mt][kt], zh + lds_off[mt][kt]);
                ldsm4(AL[mt][kt], zl + lds_off[mt][kt]);
            }
        __syncwarp();

        // ---- B fragments (L1-resident after first iter) ----
        uint2 bf[16];
#pragma unroll
        for (int t = 0; t < 16; ++t) bf[t] = BFG[t * 32 + lane];

        // ---- layer 1 MMA + fused layer 2 epilogue ----
        u64 rs2[4];
#pragma unroll
        for (int j = 0; j < 4; ++j) rs2[j] = pk2(0.0f, 0.0f);

#pragma unroll
        for (int nt = 0; nt < 4; ++nt) {
#pragma unroll
            for (int mt = 0; mt < 2; ++mt) {
                float d[4] = {0.0f, 0.0f, 0.0f, 0.0f};
                mma_bf16(d, AH[mt][0], bf[0 + nt]);        // Z_hi @ W_hi (k0)
                mma_bf16(d, AH[mt][1], bf[4 + nt]);        // Z_hi @ W_hi (k1)
                mma_bf16(d, AL[mt][0], bf[0 + nt]);        // Z_lo @ W_hi (k0)
                mma_bf16(d, AL[mt][1], bf[4 + nt]);        // Z_lo @ W_hi (k1)
                mma_bf16(d, AH[mt][0], bf[8 + nt]);        // Z_hi @ W_lo (k0)
                mma_bf16(d, AH[mt][1], bf[12 + nt]);       // Z_hi @ W_lo (k1)

                float t0 = tanh_approx(d[0] + b1c[2 * nt]);
                float t1 = tanh_approx(d[1] + b1c[2 * nt + 1]);
                rs2[2 * mt] = ffma2(pk2(w2c[2 * nt], w2c[2 * nt + 1]),
                                    pk2(t0, t1), rs2[2 * mt]);
                float t2 = tanh_approx(d[2] + b1c[2 * nt]);
                float t3 = tanh_approx(d[3] + b1c[2 * nt + 1]);
                rs2[2 * mt + 1] = ffma2(pk2(w2c[2 * nt], w2c[2 * nt + 1]),
                                        pk2(t2, t3), rs2[2 * mt + 1]);
            }
        }

        // ---- quad reduce + store ----
        float rs[4];
#pragma unroll
        for (int j = 0; j < 4; ++j) {
            float2 p = upk2(rs2[j]);
            float v = p.x + p.y;
            v += __shfl_xor_sync(0xffffffffu, v, 1);
            v += __shfl_xor_sync(0xffffffffu, v, 2);
            rs[j] = v;
        }
        const int row = (lane >> 2) + 8 * (lane & 3);
        out[sbase + row] = rs[lane & 3] + b2v;
    }
}

extern "C" void kernel_launch(void* const* d_in, const int* in_sizes, int n_in,
                              void* d_out, int out_size)
{
    const float* q  = (const float*)d_in[0];
    const float* w0 = (const float*)d_in[1];
    const float* b0 = (const float*)d_in[2];
    const float* w1 = (const float*)d_in[3];
    const float* b1 = (const float*)d_in[4];
    const float* w2 = (const float*)d_in[5];
    const float* b2 = (const float*)d_in[6];
    float* out = (float*)d_out;

    prep_kernel<<<17, TPB>>>(w0, b0, w1, b1, w2, b2);

    void* sym = nullptr; void* stg = nullptr;
    cudaGetSymbolAddress(&sym, CW4);
    cudaGetSymbolAddress(&stg, DSTG);
    cudaMemcpyAsync(sym, stg, 1348 * sizeof(float), cudaMemcpyDeviceToDevice);

    const int B = in_sizes[0] / NIN;                 // 2097152
    const int blocks = B / (TPB * ITERS);            // 4096
    WarpTileMLP_kernel<<<blocks, TPB>>>(q, out);
}

// round 12
// speedup vs baseline: 1.1907x; 1.1206x over previous
#include <cuda_runtime.h>
#include <cuda_bf16.h>
#include <cstdint>

#define NIN 7
#define H   32
#define TPB 128
#define ITERS 4          // 128 samples per CTA per iter

typedef unsigned long long u64;
typedef unsigned int u32;

// ---------------- constant weight image --------------------------------------
//  floats: b0 @1248, b1 @1280, w2 @1312, b2 @1344  (w0t/w1t slots kept for layout)
__constant__ float4 CW4[337];
__device__ float DSTG[1348];
// Layer-1 B fragments (m16n8k16, PTX layout): t = hl*8 + kt*4 + nt
__device__ uint2 BFG[512];
// Layer-0 B fragments: t = op*4 + nt (op 0: [W0_hi|W0_hi], op 1: [W0_lo|0])
__device__ uint2 BFG0[256];

__device__ __forceinline__ float cwf(int fidx) { return ((const float*)CW4)[fidx]; }

// ---------------- scalar helpers ----------------
__device__ __forceinline__ u64 pk2(float a, float b) {
    u64 r; asm("mov.b64 %0, {%1, %2};" : "=l"(r) : "f"(a), "f"(b)); return r;
}
__device__ __forceinline__ float2 upk2(u64 v) {
    float2 f; asm("mov.b64 {%0, %1}, %2;" : "=f"(f.x), "=f"(f.y) : "l"(v)); return f;
}
__device__ __forceinline__ u64 ffma2(u64 a, u64 b, u64 c) {
    u64 r; asm("fma.rn.f32x2 %0, %1, %2, %3;" : "=l"(r) : "l"(a), "l"(b), "l"(c)); return r;
}
__device__ __forceinline__ float tanh_approx(float x) {
    float r; asm("tanh.approx.f32 %0, %1;" : "=f"(r) : "f"(x)); return r;
}
// lower 16 bits = bf16(a), upper = bf16(b)
__device__ __forceinline__ u32 bf16x2_of(float a, float b) {
    u32 r; asm("cvt.rn.bf16x2.f32 %0, %1, %2;" : "=r"(r) : "f"(b), "f"(a)); return r;
}
__device__ __forceinline__ u32 smem_u32(const void* p) {
    u32 a; asm("{ .reg .u64 t; cvta.to.shared.u64 t, %1; cvt.u32.u64 %0, t; }"
               : "=r"(a) : "l"(p));
    return a;
}
__device__ __forceinline__ void ldsm4(u32* r, u32 addr) {
    asm volatile("ldmatrix.sync.aligned.m8n8.x4.shared.b16 {%0,%1,%2,%3}, [%4];"
                 : "=r"(r[0]), "=r"(r[1]), "=r"(r[2]), "=r"(r[3]) : "r"(addr));
}
__device__ __forceinline__ void mma_bf16(float* d, const u32* a, uint2 b) {
    asm volatile(
        "mma.sync.aligned.m16n8k16.row.col.f32.bf16.bf16.f32 "
        "{%0,%1,%2,%3}, {%4,%5,%6,%7}, {%8,%9}, {%0,%1,%2,%3};"
        : "+f"(d[0]), "+f"(d[1]), "+f"(d[2]), "+f"(d[3])
        : "r"(a[0]), "r"(a[1]), "r"(a[2]), "r"(a[3]), "r"(b.x), "r"(b.y));
}

// ---------------- prep kernel ----------------
__global__ void prep_kernel(const float* __restrict__ w0, const float* __restrict__ b0,
                            const float* __restrict__ w1, const float* __restrict__ b1,
                            const float* __restrict__ w2, const float* __restrict__ b2)
{
    int g = blockIdx.x * blockDim.x + threadIdx.x;
    int stride = gridDim.x * blockDim.x;

    for (int k = g; k < 1348; k += stride) {
        if (k < 224) {
            int i = k >> 5, h = k & 31;
            DSTG[k] = w0[h * NIN + i];
        } else if (k < 1248) {
            int kk = k - 224;
            int i = kk >> 5, h = kk & 31;
            DSTG[k] = w1[h * H + i];
        } else if (k < 1280) DSTG[k] = b0[k - 1248];
        else if (k < 1312)   DSTG[k] = b1[k - 1280];
        else if (k < 1344)   DSTG[k] = w2[k - 1312];
        else                 DSTG[k] = b2[0];
    }

    // Layer-1 B frags: B[k][n] = w1[n][k]; n = 8nt + lane/4, k0 = 16kt + 2*(lane%4)
    for (int idx = g; idx < 512; idx += stride) {
        int t = idx >> 5, l = idx & 31;
        int hl = t >> 3, kt = (t >> 2) & 1, nt = t & 3;
        int n = 8 * nt + (l >> 2);
        int k0 = 16 * kt + 2 * (l & 3);
        int ks[4] = { k0, k0 + 1, k0 + 8, k0 + 9 };
        u32 p[4];
        for (int j = 0; j < 4; ++j) {
            float w = w1[n * H + ks[j]];
            __nv_bfloat16 hi = __float2bfloat16(w);
            union { __nv_bfloat16 h; unsigned short s; } c;
            if (hl == 0) c.h = hi;
            else         c.h = __float2bfloat16(w - __bfloat162float(hi));
            p[j] = c.s;
        }
        BFG[idx] = make_uint2(p[0] | (p[1] << 16), p[2] | (p[3] << 16));
    }

    // Layer-0 B frags (K=16): op 0 => B[k][n] = W0_hi[n][k%8] for k!=7,15 (dup halves)
    //                         op 1 => B[k][n] = W0_lo[n][k] for k<7, else 0
    for (int idx = g; idx < 256; idx += stride) {
        int t = idx >> 5, l = idx & 31;
        int op = t >> 2, nt = t & 3;
        int n = 8 * nt + (l >> 2);
        int k0 = 2 * (l & 3);
        int ks[4] = { k0, k0 + 1, k0 + 8, k0 + 9 };
        u32 p[4];
        for (int j = 0; j < 4; ++j) {
            int k = ks[j];
            float val = 0.0f;
            if (op == 0) {
                int i = (k < 8) ? k : (k - 8);
                if (i < NIN) {
                    float w = w0[n * NIN + i];
                    val = __bfloat162float(__float2bfloat16(w));
                }
            } else {
                if (k < NIN) {
                    float w = w0[n * NIN + k];
                    float hi = __bfloat162float(__float2bfloat16(w));
                    val = w - hi;
                }
            }
            union { __nv_bfloat16 h; unsigned short s; } c;
            c.h = __float2bfloat16(val);
            p[j] = c.s;
        }
        BFG0[idx] = make_uint2(p[0] | (p[1] << 16), p[2] | (p[3] << 16));
    }
}

// ---------------- main kernel ----------------
__global__ __launch_bounds__(TPB, 4)
void WarpTileMLP_kernel(const float* __restrict__ q, float* __restrict__ out)
{
    // per-warp input staging: 32 rows x 32B ([x_hi(7),pad | x_lo(7),pad] bf16)
    __shared__ __align__(16) char zstage[4][1024];

    const int tid  = threadIdx.x;
    const int wid  = tid >> 5;
    const int lane = tid & 31;

    const u32 sbeg = smem_u32(&zstage[wid][0]);

    // STS offsets: row = lane, logical chunk c at phys (c ^ ((row>>2)&1))
    const u32 sts0 = (u32)lane * 32u + (u32)(((0 ^ ((lane >> 2) & 1))) * 16);
    const u32 sts1 = (u32)lane * 32u + (u32)(((1 ^ ((lane >> 2) & 1))) * 16);

    // ldmatrix A0 offsets: row = 16mt + r16, logical chunk cb = lane>>4
    u32 lds0[2];
    {
        int r16 = lane & 15, cb = lane >> 4;
#pragma unroll
        for (int mt = 0; mt < 2; ++mt)
            lds0[mt] = (u32)((16 * mt + r16) * 32 +
                             ((cb ^ ((r16 >> 2) & 1)) * 16));
    }

    // per-lane bias/weight constants in fragment-column layout:
    // col(nt, j) = 8nt + 2*(lane&3) + j
    float b0c[8], b1c[8], w2c[8];
#pragma unroll
    for (int nt = 0; nt < 4; ++nt)
#pragma unroll
        for (int j = 0; j < 2; ++j) {
            int col = 8 * nt + 2 * (lane & 3) + j;
            b0c[nt * 2 + j] = cwf(1248 + col);
            b1c[nt * 2 + j] = cwf(1280 + col);
            w2c[nt * 2 + j] = cwf(1312 + col);
        }
    const float b2v = cwf(1344);

    // prefetch iter-0 inputs
    float x[NIN];
    {
        const float* qr = q + (((long)blockIdx.x * ITERS) * TPB + wid * 32 + lane) * NIN;
#pragma unroll
        for (int i = 0; i < NIN; ++i) x[i] = __ldg(qr + i);
    }

    for (int it = 0; it < ITERS; ++it) {
        const long sbase = (((long)blockIdx.x * ITERS + it) * TPB) + wid * 32;

        // ---- split x into bf16 hi/lo and stage one 32B row ----
        u32 xh[4], xl[4];
        {
            float xs[8];
#pragma unroll
            for (int i = 0; i < NIN; ++i) xs[i] = x[i];
            xs[7] = 0.0f;
#pragma unroll
            for (int p = 0; p < 4; ++p) {
                u32 hp = bf16x2_of(xs[2 * p], xs[2 * p + 1]);
                float h0 = __uint_as_float(hp << 16);
                float h1 = __uint_as_float(hp & 0xFFFF0000u);
                xh[p] = hp;
                xl[p] = bf16x2_of(xs[2 * p] - h0, xs[2 * p + 1] - h1);
            }
        }
        asm volatile("st.shared.v4.b32 [%0], {%1,%2,%3,%4};" ::
            "r"(sbeg + sts0), "r"(xh[0]), "r"(xh[1]), "r"(xh[2]), "r"(xh[3]) : "memory");
        asm volatile("st.shared.v4.b32 [%0], {%1,%2,%3,%4};" ::
            "r"(sbeg + sts1), "r"(xl[0]), "r"(xl[1]), "r"(xl[2]), "r"(xl[3]) : "memory");
        __syncwarp();

        // ---- prefetch next iter's inputs (x is dead now) ----
        if (it + 1 < ITERS) {
            const float* qn = q + (sbase + TPB + lane) * NIN;
#pragma unroll
            for (int i = 0; i < NIN; ++i) x[i] = __ldg(qn + i);
        }

        // ---- A0 fragments ----
        u32 A0[2][4];
        ldsm4(A0[0], sbeg + lds0[0]);
        ldsm4(A0[1], sbeg + lds0[1]);
        __syncwarp();

        // ---- layer 0 MMA + bias + tanh + bf16 split -> layer-1 A fragments --
        // D-tile (mt,nt) regs (d0,d1 ; d2,d3) become A-frag regs:
        //   AH[mt][kt] = { pk(z0,z1)@nt=2kt, pk(z2,z3)@nt=2kt,
        //                  pk(z0,z1)@nt=2kt+1, pk(z2,z3)@nt=2kt+1 }
        u32 AH[2][2][4], AL[2][2][4];
#pragma unroll
        for (int kt = 0; kt < 2; ++kt) {
            uint2 bhh0 = BFG0[(0 + 2 * kt) * 32 + lane];
            uint2 bhh1 = BFG0[(0 + 2 * kt + 1) * 32 + lane];
            uint2 blo0 = BFG0[(16 + 2 * kt * 4 - 2 * kt * 4 + (4 + 2 * kt)) * 0 +
                              (4 + 2 * kt) * 32 + lane];
            uint2 blo1 = BFG0[(4 + 2 * kt + 1) * 32 + lane];
#pragma unroll
            for (int mt = 0; mt < 2; ++mt) {
                float d0[4] = {0.f, 0.f, 0.f, 0.f};
                float d1[4] = {0.f, 0.f, 0.f, 0.f};
                mma_bf16(d0, A0[mt], bhh0);   // x@W0_hi   (tile nt=2kt)
                mma_bf16(d0, A0[mt], blo0);   // x_hi@W0_lo
                mma_bf16(d1, A0[mt], bhh1);   // tile nt=2kt+1
                mma_bf16(d1, A0[mt], blo1);

                // tile nt = 2kt
                float z0 = tanh_approx(d0[0] + b0c[2 * (2 * kt)]);
                float z1 = tanh_approx(d0[1] + b0c[2 * (2 * kt) + 1]);
                float z2 = tanh_approx(d0[2] + b0c[2 * (2 * kt)]);
                float z3 = tanh_approx(d0[3] + b0c[2 * (2 * kt) + 1]);
                u32 h01 = bf16x2_of(z0, z1);
                u32 h23 = bf16x2_of(z2, z3);
                AH[mt][kt][0] = h01;
                AH[mt][kt][1] = h23;
                AL[mt][kt][0] = bf16x2_of(z0 - __uint_as_float(h01 << 16),
                                          z1 - __uint_as_float(h01 & 0xFFFF0000u));
                AL[mt][kt][1] = bf16x2_of(z2 - __uint_as_float(h23 << 16),
                                          z3 - __uint_as_float(h23 & 0xFFFF0000u));

                // tile nt = 2kt+1
                float y0 = tanh_approx(d1[0] + b0c[2 * (2 * kt + 1)]);
                float y1 = tanh_approx(d1[1] + b0c[2 * (2 * kt + 1) + 1]);
                float y2 = tanh_approx(d1[2] + b0c[2 * (2 * kt + 1)]);
                float y3 = tanh_approx(d1[3] + b0c[2 * (2 * kt + 1) + 1]);
                u32 g01 = bf16x2_of(y0, y1);
                u32 g23 = bf16x2_of(y2, y3);
                AH[mt][kt][2] = g01;
                AH[mt][kt][3] = g23;
                AL[mt][kt][2] = bf16x2_of(y0 - __uint_as_float(g01 << 16),
                                          y1 - __uint_as_float(g01 & 0xFFFF0000u));
                AL[mt][kt][3] = bf16x2_of(y2 - __uint_as_float(g23 << 16),
                                          y3 - __uint_as_float(g23 & 0xFFFF0000u));
            }
        }

        // ---- layer-1 B fragments ----
        uint2 bf[16];
#pragma unroll
        for (int t = 0; t < 16; ++t) bf[t] = BFG[t * 32 + lane];

        // ---- layer 1 MMA + fused layer 2 epilogue (identical to R9) ----
        u64 rs2[4];
#pragma unroll
        for (int j = 0; j < 4; ++j) rs2[j] = pk2(0.0f, 0.0f);

#pragma unroll
        for (int nt = 0; nt < 4; ++nt) {
#pragma unroll
            for (int mt = 0; mt < 2; ++mt) {
                float d[4] = {0.0f, 0.0f, 0.0f, 0.0f};
                mma_bf16(d, AH[mt][0], bf[0 + nt]);        // Z_hi @ W_hi (k0)
                mma_bf16(d, AH[mt][1], bf[4 + nt]);        // Z_hi @ W_hi (k1)
                mma_bf16(d, AL[mt][0], bf[0 + nt]);        // Z_lo @ W_hi (k0)
                mma_bf16(d, AL[mt][1], bf[4 + nt]);        // Z_lo @ W_hi (k1)
                mma_bf16(d, AH[mt][0], bf[8 + nt]);        // Z_hi @ W_lo (k0)
                mma_bf16(d, AH[mt][1], bf[12 + nt]);       // Z_hi @ W_lo (k1)

                float t0 = tanh_approx(d[0] + b1c[2 * nt]);
                float t1 = tanh_approx(d[1] + b1c[2 * nt + 1]);
                rs2[2 * mt] = ffma2(pk2(w2c[2 * nt], w2c[2 * nt + 1]),
                                    pk2(t0, t1), rs2[2 * mt]);
                float t2 = tanh_approx(d[2] + b1c[2 * nt]);
                float t3 = tanh_approx(d[3] + b1c[2 * nt + 1]);
                rs2[2 * mt + 1] = ffma2(pk2(w2c[2 * nt], w2c[2 * nt + 1]),
                                        pk2(t2, t3), rs2[2 * mt + 1]);
            }
        }

        // ---- quad reduce + store ----
        float rs[4];
#pragma unroll
        for (int j = 0; j < 4; ++j) {
            float2 p = upk2(rs2[j]);
            float v = p.x + p.y;
            v += __shfl_xor_sync(0xffffffffu, v, 1);
            v += __shfl_xor_sync(0xffffffffu, v, 2);
            rs[j] = v;
        }
        const int row = (lane >> 2) + 8 * (lane & 3);
        out[sbase + row] = rs[lane & 3] + b2v;
        __syncwarp();   // staging reuse: all ldsm done before next iter's STS
    }
}

extern "C" void kernel_launch(void* const* d_in, const int* in_sizes, int n_in,
                              void* d_out, int out_size)
{
    const float* q  = (const float*)d_in[0];
    const float* w0 = (const float*)d_in[1];
    const float* b0 = (const float*)d_in[2];
    const float* w1 = (const float*)d_in[3];
    const float* b1 = (const float*)d_in[4];
    const float* w2 = (const float*)d_in[5];
    const float* b2 = (const float*)d_in[6];
    float* out = (float*)d_out;

    prep_kernel<<<17, TPB>>>(w0, b0, w1, b1, w2, b2);

    void* sym = nullptr; void* stg = nullptr;
    cudaGetSymbolAddress(&sym, CW4);
    cudaGetSymbolAddress(&stg, DSTG);
    cudaMemcpyAsync(sym, stg, 1348 * sizeof(float), cudaMemcpyDeviceToDevice);

    const int B = in_sizes[0] / NIN;                 // 2097152
    const int blocks = B / (TPB * ITERS);            // 4096
    WarpTileMLP_kernel<<<blocks, TPB>>>(q, out);
}